// round 4
// baseline (speedup 1.0000x reference)
#include <cuda_runtime.h>
#include <math.h>

// Problem constants
#define BB 2
#define LL 2048
#define DD 1024
#define HH 16
#define HDD 64
#define MTOT (BB*LL)   // 4096

// Scratch (allocation-free rule: __device__ globals)
__device__ float g_q[MTOT * DD];
__device__ float g_k[MTOT * DD];
__device__ float g_v[MTOT * DD];
__device__ float g_ctx[MTOT * DD];

// ---------------------------------------------------------------------------
// SGEMM: C[M=4096][N=1024] = A[4096][1024] @ W[1024][1024] + bias
// BM=BN=128, BK=8, 256 threads, 8x8 micro-tile.
// ---------------------------------------------------------------------------
__device__ __forceinline__ void gemm_body(const float* __restrict__ A,
                                          const float* __restrict__ W,
                                          const float* __restrict__ bias,
                                          float* __restrict__ C)
{
    __shared__ float As[8][132];   // [k][m], padded
    __shared__ float Bs[8][132];   // [k][n], padded

    const int tid = threadIdx.x;
    const int tx = tid & 15;       // 0..15 -> n sub-tile
    const int ty = tid >> 4;       // 0..15 -> m sub-tile
    const int m0 = blockIdx.y * 128;
    const int n0 = blockIdx.x * 128;

    float acc[8][8];
#pragma unroll
    for (int i = 0; i < 8; i++)
#pragma unroll
        for (int j = 0; j < 8; j++) acc[i][j] = 0.0f;

    for (int k0 = 0; k0 < 1024; k0 += 8) {
        // Load A tile 128x8 (transposed into As[k][m])
        {
            const int r  = tid >> 1;            // 0..127
            const int c4 = (tid & 1) * 4;       // 0 or 4
            float4 av = *(const float4*)&A[(size_t)(m0 + r) * 1024 + k0 + c4];
            As[c4 + 0][r] = av.x;
            As[c4 + 1][r] = av.y;
            As[c4 + 2][r] = av.z;
            As[c4 + 3][r] = av.w;
        }
        // Load W tile 8x128
        {
            const int r = tid >> 5;             // 0..7
            const int c = (tid & 31) * 4;       // 0..124
            *(float4*)&Bs[r][c] = *(const float4*)&W[(size_t)(k0 + r) * 1024 + n0 + c];
        }
        __syncthreads();

#pragma unroll
        for (int k = 0; k < 8; k++) {
            float a[8], b[8];
            *(float4*)&a[0] = *(const float4*)&As[k][ty * 4];
            *(float4*)&a[4] = *(const float4*)&As[k][64 + ty * 4];
            *(float4*)&b[0] = *(const float4*)&Bs[k][tx * 4];
            *(float4*)&b[4] = *(const float4*)&Bs[k][64 + tx * 4];
#pragma unroll
            for (int i = 0; i < 8; i++)
#pragma unroll
                for (int j = 0; j < 8; j++)
                    acc[i][j] += a[i] * b[j];
        }
        __syncthreads();
    }

    // Write back with bias
    float4 bv0 = *(const float4*)&bias[n0 + tx * 4];
    float4 bv1 = *(const float4*)&bias[n0 + 64 + tx * 4];
#pragma unroll
    for (int half = 0; half < 2; half++) {
        const int mrow0 = m0 + half * 64 + ty * 4;
#pragma unroll
        for (int i = 0; i < 4; i++) {
            const int ii = half * 4 + i;
            float4 o0, o1;
            o0.x = acc[ii][0] + bv0.x; o0.y = acc[ii][1] + bv0.y;
            o0.z = acc[ii][2] + bv0.z; o0.w = acc[ii][3] + bv0.w;
            o1.x = acc[ii][4] + bv1.x; o1.y = acc[ii][5] + bv1.y;
            o1.z = acc[ii][6] + bv1.z; o1.w = acc[ii][7] + bv1.w;
            *(float4*)&C[(size_t)(mrow0 + i) * 1024 + n0 + tx * 4]      = o0;
            *(float4*)&C[(size_t)(mrow0 + i) * 1024 + n0 + 64 + tx * 4] = o1;
        }
    }
}

__global__ __launch_bounds__(256) void qkv_gemm_kernel(
    const float* __restrict__ A,
    const float* __restrict__ Wq, const float* __restrict__ bq,
    const float* __restrict__ Wk, const float* __restrict__ bk,
    const float* __restrict__ Wv, const float* __restrict__ bv)
{
    const float* W; const float* bias; float* C;
    if (blockIdx.z == 0)      { W = Wq; bias = bq; C = g_q; }
    else if (blockIdx.z == 1) { W = Wk; bias = bk; C = g_k; }
    else                      { W = Wv; bias = bv; C = g_v; }
    gemm_body(A, W, bias, C);
}

__global__ __launch_bounds__(256) void out_gemm_kernel(
    const float* __restrict__ W, const float* __restrict__ bias,
    float* __restrict__ out)
{
    gemm_body(g_ctx, W, bias, out);
}

// ---------------------------------------------------------------------------
// Flash-style attention: one block = one (b, h, 64-query tile).
// Online softmax over 32 KV tiles of 64. HD = 64.
// Dynamic smem: QsT[64][68] + KsT[64][68] + Vs[64][68] + Ps[64][68]
// ---------------------------------------------------------------------------
#define TPAD 68
#define ATTN_SMEM (4 * 64 * TPAD * 4)

__global__ __launch_bounds__(256) void attn_kernel(const float* __restrict__ mask,
                                                   float* __restrict__ ctx)
{
    extern __shared__ float smem[];
    float* QsT = smem;                    // [d][q]  stride TPAD
    float* KsT = QsT + 64 * TPAD;         // [d][n]
    float* Vs  = KsT + 64 * TPAD;         // [n][d]
    float* Ps  = Vs  + 64 * TPAD;         // [q][n]

    __shared__ float m_sh[64], l_sh[64], alpha_sh[64];

    const int tid = threadIdx.x;
    const int tx = tid & 15;   // n / d sub-tile
    const int ty = tid >> 4;   // q sub-tile
    const int b = blockIdx.y / HH;
    const int h = blockIdx.y % HH;
    const int q0 = blockIdx.x * 64;

    const float* qptr = g_q + ((size_t)b * LL + q0) * DD + h * HDD;
    const float* kbase = g_k + (size_t)b * LL * DD + h * HDD;
    const float* vbase = g_v + (size_t)b * LL * DD + h * HDD;
    const float* mrow = mask + (size_t)b * LL;

    // Load Q tile (scaled by 1/sqrt(64)), transposed
    for (int idx = tid; idx < 4096; idx += 256) {
        const int r = idx >> 6, c = idx & 63;
        QsT[c * TPAD + r] = qptr[(size_t)r * DD + c] * 0.125f;
    }
    if (tid < 64) { m_sh[tid] = -INFINITY; l_sh[tid] = 0.0f; }

    float acc[4][4];
#pragma unroll
    for (int i = 0; i < 4; i++)
#pragma unroll
        for (int j = 0; j < 4; j++) acc[i][j] = 0.0f;

    for (int t = 0; t < LL / 64; t++) {
        __syncthreads();   // prior O-update done before overwriting K/V
        const float* kptr = kbase + (size_t)t * 64 * DD;
        const float* vptr = vbase + (size_t)t * 64 * DD;
        for (int idx = tid; idx < 4096; idx += 256) {
            const int r = idx >> 6, c = idx & 63;
            KsT[c * TPAD + r] = kptr[(size_t)r * DD + c];
            Vs[r * TPAD + c]  = vptr[(size_t)r * DD + c];
        }
        __syncthreads();

        // S = Q @ K^T  (4x4 fragment)
        float s[4][4];
#pragma unroll
        for (int i = 0; i < 4; i++)
#pragma unroll
            for (int j = 0; j < 4; j++) s[i][j] = 0.0f;

#pragma unroll 8
        for (int d = 0; d < 64; d++) {
            float a[4], bb[4];
            *(float4*)a  = *(const float4*)&QsT[d * TPAD + ty * 4];
            *(float4*)bb = *(const float4*)&KsT[d * TPAD + tx * 4];
#pragma unroll
            for (int i = 0; i < 4; i++)
#pragma unroll
                for (int j = 0; j < 4; j++)
                    s[i][j] += a[i] * bb[j];
        }

        // additive mask, write scores to Ps
        const int kv0 = t * 64 + tx * 4;
        float mk[4];
        mk[0] = mrow[kv0 + 0]; mk[1] = mrow[kv0 + 1];
        mk[2] = mrow[kv0 + 2]; mk[3] = mrow[kv0 + 3];
#pragma unroll
        for (int i = 0; i < 4; i++) {
            float4 o;
            o.x = s[i][0] + mk[0]; o.y = s[i][1] + mk[1];
            o.z = s[i][2] + mk[2]; o.w = s[i][3] + mk[3];
            *(float4*)&Ps[(ty * 4 + i) * TPAD + tx * 4] = o;
        }
        __syncthreads();

        // online softmax per row (64 threads, one row each)
        if (tid < 64) {
            float* prow = &Ps[tid * TPAD];
            float mr = -INFINITY;
#pragma unroll 8
            for (int c = 0; c < 64; c++) mr = fmaxf(mr, prow[c]);
            const float mold = m_sh[tid];
            const float mnew = fmaxf(mold, mr);
            const float a = expf(mold - mnew);
            float ssum = 0.0f;
#pragma unroll 8
            for (int c = 0; c < 64; c++) {
                const float p = expf(prow[c] - mnew);
                prow[c] = p;
                ssum += p;
            }
            l_sh[tid] = l_sh[tid] * a + ssum;
            m_sh[tid] = mnew;
            alpha_sh[tid] = a;
        }
        __syncthreads();

        // O = O*alpha + P @ V
#pragma unroll
        for (int i = 0; i < 4; i++) {
            const float a = alpha_sh[ty * 4 + i];
#pragma unroll
            for (int j = 0; j < 4; j++) acc[i][j] *= a;
        }
#pragma unroll 8
        for (int k = 0; k < 64; k++) {
            float p[4], v[4];
            p[0] = Ps[(ty * 4 + 0) * TPAD + k];
            p[1] = Ps[(ty * 4 + 1) * TPAD + k];
            p[2] = Ps[(ty * 4 + 2) * TPAD + k];
            p[3] = Ps[(ty * 4 + 3) * TPAD + k];
            *(float4*)v = *(const float4*)&Vs[k * TPAD + tx * 4];
#pragma unroll
            for (int i = 0; i < 4; i++)
#pragma unroll
                for (int j = 0; j < 4; j++)
                    acc[i][j] += p[i] * v[j];
        }
    }
    __syncthreads();

    // normalize + write ctx in [B, L, D] layout (heads re-interleaved)
#pragma unroll
    for (int i = 0; i < 4; i++) {
        const int row = ty * 4 + i;
        const float inv = 1.0f / l_sh[row];
        float4 o;
        o.x = acc[i][0] * inv; o.y = acc[i][1] * inv;
        o.z = acc[i][2] * inv; o.w = acc[i][3] * inv;
        *(float4*)&ctx[((size_t)b * LL + q0 + row) * DD + h * HDD + tx * 4] = o;
    }
}

// ---------------------------------------------------------------------------
extern "C" void kernel_launch(void* const* d_in, const int* in_sizes, int n_in,
                              void* d_out, int out_size)
{
    const float* hs   = (const float*)d_in[0];
    const float* mask = (const float*)d_in[1];
    const float* Wq = (const float*)d_in[2]; const float* bq = (const float*)d_in[3];
    const float* Wk = (const float*)d_in[4]; const float* bk = (const float*)d_in[5];
    const float* Wv = (const float*)d_in[6]; const float* bv = (const float*)d_in[7];
    const float* Wo = (const float*)d_in[8]; const float* bo = (const float*)d_in[9];
    float* out = (float*)d_out;

    cudaFuncSetAttribute(attn_kernel, cudaFuncAttributeMaxDynamicSharedMemorySize,
                         ATTN_SMEM);

    float* ctx_ptr = nullptr;
    cudaGetSymbolAddress((void**)&ctx_ptr, g_ctx);

    // 1) QKV projections: grid (N/128, M/128, 3)
    dim3 ggrid(1024 / 128, 4096 / 128, 3);
    qkv_gemm_kernel<<<ggrid, 256>>>(hs, Wq, bq, Wk, bk, Wv, bv);

    // 2) Attention: grid (L/64, B*H)
    dim3 agrid(LL / 64, BB * HH);
    attn_kernel<<<agrid, 256, ATTN_SMEM>>>(mask, ctx_ptr);

    // 3) Output projection
    dim3 ogrid(1024 / 128, 4096 / 128, 1);
    out_gemm_kernel<<<ogrid, 256>>>(Wo, bo, out);
}

// round 5
// speedup vs baseline: 2.6806x; 2.6806x over previous
#include <cuda_runtime.h>
#include <math.h>
#include <stdint.h>

// Problem constants
#define BB 2
#define LL 2048
#define DD 1024
#define HH 16
#define HDD 64
#define MTOT (BB*LL)   // 4096

// Scratch (allocation-free rule: __device__ globals)
__device__ float g_q[MTOT * DD];
__device__ float g_k[MTOT * DD];
__device__ float g_v[MTOT * DD];
__device__ float g_ctx[MTOT * DD];

// ---------------------------------------------------------------------------
// tf32 helpers
// ---------------------------------------------------------------------------
__device__ __forceinline__ uint32_t f2tf(float f) {
    uint32_t r;
    asm("cvt.rna.tf32.f32 %0, %1;" : "=r"(r) : "f"(f));
    return r;
}

__device__ __forceinline__ void mma_tf32(float* d, const uint32_t* a, const uint32_t* b) {
    asm volatile(
        "mma.sync.aligned.m16n8k8.row.col.f32.tf32.tf32.f32 "
        "{%0,%1,%2,%3}, {%4,%5,%6,%7}, {%8,%9}, {%0,%1,%2,%3};\n"
        : "+f"(d[0]), "+f"(d[1]), "+f"(d[2]), "+f"(d[3])
        : "r"(a[0]), "r"(a[1]), "r"(a[2]), "r"(a[3]), "r"(b[0]), "r"(b[1]));
}

// ---------------------------------------------------------------------------
// Tensor-core SGEMM (tf32): C[M=4096][N=1024] = A @ W + bias
// Block 128x128, BK=32, 8 warps (2x4), warp tile 64x32 (4x4 m16n8k8 tiles).
// As[m][k] stride 36; Bs[k][n] stride 136. Double-buffered.
// ---------------------------------------------------------------------------
#define G_ASTRIDE 36
#define G_BSTRIDE 136
#define G_ABUF (128 * G_ASTRIDE)      // 4608 words
#define G_BBUF (32 * G_BSTRIDE)       // 4352 words
#define G_BUF  (G_ABUF + G_BBUF)      // 8960 words
#define GEMM_SMEM (2 * G_BUF * 4)     // 71680 bytes

__device__ __forceinline__ void gemm_tc_body(const float* __restrict__ A,
                                             const float* __restrict__ W,
                                             const float* __restrict__ bias,
                                             float* __restrict__ C)
{
    extern __shared__ float smemf[];
    uint32_t* smem = (uint32_t*)smemf;

    const int tid  = threadIdx.x;
    const int warp = tid >> 5;
    const int lane = tid & 31;
    const int g    = lane >> 2;   // groupID
    const int t    = lane & 3;    // threadID in group
    const int wm   = warp >> 2;   // 0..1
    const int wn   = warp & 3;    // 0..3
    const int m0 = blockIdx.y * 128;
    const int n0 = blockIdx.x * 128;

    // staging-load index precompute
    const int am = ( (0*256 + tid) >> 3 );            // varies per i below
    (void)am;

    float acc[4][4][4];
#pragma unroll
    for (int mt = 0; mt < 4; mt++)
#pragma unroll
        for (int nt = 0; nt < 4; nt++)
#pragma unroll
            for (int c = 0; c < 4; c++) acc[mt][nt][c] = 0.0f;

    float4 ar[4], br[4];

    // prologue: load tile 0
#pragma unroll
    for (int i = 0; i < 4; i++) {
        int idx = i * 256 + tid;
        int m = idx >> 3, q = idx & 7;
        ar[i] = *(const float4*)&A[(size_t)(m0 + m) * 1024 + 4 * q];
        int k = idx >> 5, qn = idx & 31;
        br[i] = *(const float4*)&W[(size_t)k * 1024 + n0 + 4 * qn];
    }
    // store tile 0 -> buf0
#pragma unroll
    for (int i = 0; i < 4; i++) {
        int idx = i * 256 + tid;
        int m = idx >> 3, q = idx & 7;
        uint32_t* as = smem;  // buf0
        as[m * G_ASTRIDE + 4 * q + 0] = f2tf(ar[i].x);
        as[m * G_ASTRIDE + 4 * q + 1] = f2tf(ar[i].y);
        as[m * G_ASTRIDE + 4 * q + 2] = f2tf(ar[i].z);
        as[m * G_ASTRIDE + 4 * q + 3] = f2tf(ar[i].w);
        int k = idx >> 5, qn = idx & 31;
        uint32_t* bs = smem + G_ABUF;
        bs[k * G_BSTRIDE + 4 * qn + 0] = f2tf(br[i].x);
        bs[k * G_BSTRIDE + 4 * qn + 1] = f2tf(br[i].y);
        bs[k * G_BSTRIDE + 4 * qn + 2] = f2tf(br[i].z);
        bs[k * G_BSTRIDE + 4 * qn + 3] = f2tf(br[i].w);
    }
    __syncthreads();

#pragma unroll 1
    for (int kt = 0; kt < 32; kt++) {
        const int cur = kt & 1;
        const uint32_t* as = smem + cur * G_BUF;
        const uint32_t* bs = smem + cur * G_BUF + G_ABUF;

        if (kt < 31) {
            const int k0 = (kt + 1) * 32;
#pragma unroll
            for (int i = 0; i < 4; i++) {
                int idx = i * 256 + tid;
                int m = idx >> 3, q = idx & 7;
                ar[i] = *(const float4*)&A[(size_t)(m0 + m) * 1024 + k0 + 4 * q];
                int k = idx >> 5, qn = idx & 31;
                br[i] = *(const float4*)&W[(size_t)(k0 + k) * 1024 + n0 + 4 * qn];
            }
        }

#pragma unroll
        for (int ks = 0; ks < 4; ks++) {
            uint32_t afr[4][4], bfr[4][2];
#pragma unroll
            for (int mt = 0; mt < 4; mt++) {
                const uint32_t* base = as + (wm * 64 + mt * 16 + g) * G_ASTRIDE + ks * 8 + t;
                afr[mt][0] = base[0];
                afr[mt][1] = base[8 * G_ASTRIDE];
                afr[mt][2] = base[4];
                afr[mt][3] = base[8 * G_ASTRIDE + 4];
            }
#pragma unroll
            for (int nt = 0; nt < 4; nt++) {
                const uint32_t* base = bs + (ks * 8 + t) * G_BSTRIDE + wn * 32 + nt * 8 + g;
                bfr[nt][0] = base[0];
                bfr[nt][1] = base[4 * G_BSTRIDE];
            }
#pragma unroll
            for (int mt = 0; mt < 4; mt++)
#pragma unroll
                for (int nt = 0; nt < 4; nt++)
                    mma_tf32(acc[mt][nt], afr[mt], bfr[nt]);
        }

        if (kt < 31) {
            uint32_t* as2 = smem + (cur ^ 1) * G_BUF;
            uint32_t* bs2 = as2 + G_ABUF;
#pragma unroll
            for (int i = 0; i < 4; i++) {
                int idx = i * 256 + tid;
                int m = idx >> 3, q = idx & 7;
                as2[m * G_ASTRIDE + 4 * q + 0] = f2tf(ar[i].x);
                as2[m * G_ASTRIDE + 4 * q + 1] = f2tf(ar[i].y);
                as2[m * G_ASTRIDE + 4 * q + 2] = f2tf(ar[i].z);
                as2[m * G_ASTRIDE + 4 * q + 3] = f2tf(ar[i].w);
                int k = idx >> 5, qn = idx & 31;
                bs2[k * G_BSTRIDE + 4 * qn + 0] = f2tf(br[i].x);
                bs2[k * G_BSTRIDE + 4 * qn + 1] = f2tf(br[i].y);
                bs2[k * G_BSTRIDE + 4 * qn + 2] = f2tf(br[i].z);
                bs2[k * G_BSTRIDE + 4 * qn + 3] = f2tf(br[i].w);
            }
        }
        __syncthreads();
    }

    // epilogue: bias + store
#pragma unroll
    for (int mt = 0; mt < 4; mt++) {
        const int r0 = m0 + wm * 64 + mt * 16 + g;
        const int r1 = r0 + 8;
#pragma unroll
        for (int nt = 0; nt < 4; nt++) {
            const int c = n0 + wn * 32 + nt * 8 + 2 * t;
            const float b0 = bias[c], b1 = bias[c + 1];
            float2 o0, o1;
            o0.x = acc[mt][nt][0] + b0; o0.y = acc[mt][nt][1] + b1;
            o1.x = acc[mt][nt][2] + b0; o1.y = acc[mt][nt][3] + b1;
            *(float2*)&C[(size_t)r0 * 1024 + c] = o0;
            *(float2*)&C[(size_t)r1 * 1024 + c] = o1;
        }
    }
}

__global__ __launch_bounds__(256, 1) void qkv_gemm_tc(
    const float* __restrict__ A,
    const float* __restrict__ Wq, const float* __restrict__ bq,
    const float* __restrict__ Wk, const float* __restrict__ bk,
    const float* __restrict__ Wv, const float* __restrict__ bv)
{
    const float* W; const float* bias; float* C;
    if (blockIdx.z == 0)      { W = Wq; bias = bq; C = g_q; }
    else if (blockIdx.z == 1) { W = Wk; bias = bk; C = g_k; }
    else                      { W = Wv; bias = bv; C = g_v; }
    gemm_tc_body(A, W, bias, C);
}

__global__ __launch_bounds__(256, 1) void out_gemm_tc(
    const float* __restrict__ W, const float* __restrict__ bias,
    float* __restrict__ out)
{
    gemm_tc_body(g_ctx, W, bias, out);
}

// ---------------------------------------------------------------------------
// Flash attention with tf32 mma. q-tile=128, kv-tile=128, HD=64, 256 threads.
// S phase: warps 2x4 (tile 64x32).  PV phase: warps 4x2 (tile 32x32).
// smem (words): Qs[128*68] Ks[128*68] Vs[128*72] Ps[128*132] mask[128] m/l/al[128]
// ---------------------------------------------------------------------------
#define QS_OFF 0
#define KS_OFF 8704
#define VS_OFF 17408
#define PS_OFF 26624
#define MK_OFF 43520
#define M_OFF  43648
#define L_OFF  43776
#define AL_OFF 43904
#define ATTN_WORDS 44032
#define ATTN_SMEM (ATTN_WORDS * 4)

__global__ __launch_bounds__(256, 1) void attn_tc(const float* __restrict__ mask,
                                                  float* __restrict__ ctx)
{
    extern __shared__ float smemf[];
    uint32_t* smem = (uint32_t*)smemf;
    float* Qs = smemf + QS_OFF;     // [q][d]  stride 68
    float* Ks = smemf + KS_OFF;     // [kv][d] stride 68
    float* Vs = smemf + VS_OFF;     // [kv][d] stride 72
    float* Ps = smemf + PS_OFF;     // [q][kv] stride 132
    float* mk = smemf + MK_OFF;
    float* m_sh = smemf + M_OFF;
    float* l_sh = smemf + L_OFF;
    float* al_sh = smemf + AL_OFF;

    const int tid  = threadIdx.x;
    const int warp = tid >> 5;
    const int lane = tid & 31;
    const int g    = lane >> 2;
    const int t    = lane & 3;
    const int wm = warp >> 2, wn = warp & 3;   // S phase
    const int pm = warp >> 1, pn = warp & 1;   // PV phase

    const int b  = blockIdx.y / HH;
    const int h  = blockIdx.y % HH;
    const int q0 = blockIdx.x * 128;

    const float* qg = g_q + ((size_t)b * LL + q0) * DD + h * HDD;
    const float* kb = g_k + (size_t)b * LL * DD + h * HDD;
    const float* vb = g_v + (size_t)b * LL * DD + h * HDD;
    const float* mrow = mask + (size_t)b * LL;

    // Load Q (scaled, tf32)
#pragma unroll
    for (int i = 0; i < 8; i++) {
        int idx = i * 256 + tid;
        int r = idx >> 4, q4 = idx & 15;
        float4 v = *(const float4*)&qg[(size_t)r * DD + 4 * q4];
        uint32_t* dst = smem + QS_OFF + r * 68 + 4 * q4;
        dst[0] = f2tf(v.x * 0.125f);
        dst[1] = f2tf(v.y * 0.125f);
        dst[2] = f2tf(v.z * 0.125f);
        dst[3] = f2tf(v.w * 0.125f);
    }
    if (tid < 128) { m_sh[tid] = -INFINITY; l_sh[tid] = 0.0f; }

    float oacc[2][4][4];
#pragma unroll
    for (int mt = 0; mt < 2; mt++)
#pragma unroll
        for (int nt = 0; nt < 4; nt++)
#pragma unroll
            for (int c = 0; c < 4; c++) oacc[mt][nt][c] = 0.0f;

#pragma unroll 1
    for (int kt = 0; kt < LL / 128; kt++) {
        __syncthreads();   // previous PV done before overwriting Ks/Vs/Ps
        const float* kg = kb + (size_t)kt * 128 * DD;
        const float* vg = vb + (size_t)kt * 128 * DD;
#pragma unroll
        for (int i = 0; i < 8; i++) {
            int idx = i * 256 + tid;
            int r = idx >> 4, q4 = idx & 15;
            float4 kv4 = *(const float4*)&kg[(size_t)r * DD + 4 * q4];
            uint32_t* kd = smem + KS_OFF + r * 68 + 4 * q4;
            kd[0] = f2tf(kv4.x); kd[1] = f2tf(kv4.y);
            kd[2] = f2tf(kv4.z); kd[3] = f2tf(kv4.w);
            float4 vv4 = *(const float4*)&vg[(size_t)r * DD + 4 * q4];
            uint32_t* vd = smem + VS_OFF + r * 72 + 4 * q4;
            vd[0] = f2tf(vv4.x); vd[1] = f2tf(vv4.y);
            vd[2] = f2tf(vv4.z); vd[3] = f2tf(vv4.w);
        }
        if (tid < 128) mk[tid] = mrow[kt * 128 + tid];
        __syncthreads();

        // ---- S = Q @ K^T ----
        float sacc[4][4][4];
#pragma unroll
        for (int mt = 0; mt < 4; mt++)
#pragma unroll
            for (int nt = 0; nt < 4; nt++)
#pragma unroll
                for (int c = 0; c < 4; c++) sacc[mt][nt][c] = 0.0f;

#pragma unroll
        for (int ks = 0; ks < 8; ks++) {
            uint32_t afr[4][4], bfr[4][2];
#pragma unroll
            for (int mt = 0; mt < 4; mt++) {
                const uint32_t* base = smem + QS_OFF + (wm * 64 + mt * 16 + g) * 68 + ks * 8 + t;
                afr[mt][0] = base[0];
                afr[mt][1] = base[8 * 68];
                afr[mt][2] = base[4];
                afr[mt][3] = base[8 * 68 + 4];
            }
#pragma unroll
            for (int nt = 0; nt < 4; nt++) {
                const uint32_t* base = smem + KS_OFF + (wn * 32 + nt * 8 + g) * 68 + ks * 8 + t;
                bfr[nt][0] = base[0];
                bfr[nt][1] = base[4];
            }
#pragma unroll
            for (int mt = 0; mt < 4; mt++)
#pragma unroll
                for (int nt = 0; nt < 4; nt++)
                    mma_tf32(sacc[mt][nt], afr[mt], bfr[nt]);
        }

        // write S + mask to Ps
#pragma unroll
        for (int mt = 0; mt < 4; mt++) {
            const int r0 = wm * 64 + mt * 16 + g;
#pragma unroll
            for (int nt = 0; nt < 4; nt++) {
                const int c = wn * 32 + nt * 8 + 2 * t;
                const float mk0 = mk[c], mk1 = mk[c + 1];
                float2 s0, s1;
                s0.x = sacc[mt][nt][0] + mk0; s0.y = sacc[mt][nt][1] + mk1;
                s1.x = sacc[mt][nt][2] + mk0; s1.y = sacc[mt][nt][3] + mk1;
                *(float2*)&Ps[r0 * 132 + c]       = s0;
                *(float2*)&Ps[(r0 + 8) * 132 + c] = s1;
            }
        }
        __syncthreads();

        // ---- online softmax: 2 lanes per row ----
        {
            const int r = tid >> 1, half = tid & 1;
            float* prow = &Ps[r * 132 + half * 64];
            float mx = -INFINITY;
#pragma unroll
            for (int i = 0; i < 16; i++) {
                float4 v = *(const float4*)&prow[i * 4];
                mx = fmaxf(mx, fmaxf(fmaxf(v.x, v.y), fmaxf(v.z, v.w)));
            }
            mx = fmaxf(mx, __shfl_xor_sync(0xFFFFFFFF, mx, 1));
            const float mold = m_sh[r];
            const float mnew = fmaxf(mold, mx);
            const float a = __expf(mold - mnew);
            float ssum = 0.0f;
            uint32_t* prowu = (uint32_t*)prow;
#pragma unroll
            for (int i = 0; i < 16; i++) {
                float4 v = *(const float4*)&prow[i * 4];
                float p0 = __expf(v.x - mnew);
                float p1 = __expf(v.y - mnew);
                float p2 = __expf(v.z - mnew);
                float p3 = __expf(v.w - mnew);
                ssum += (p0 + p1) + (p2 + p3);
                prowu[i * 4 + 0] = f2tf(p0);
                prowu[i * 4 + 1] = f2tf(p1);
                prowu[i * 4 + 2] = f2tf(p2);
                prowu[i * 4 + 3] = f2tf(p3);
            }
            ssum += __shfl_xor_sync(0xFFFFFFFF, ssum, 1);
            l_sh[r] = l_sh[r] * a + ssum;
            m_sh[r] = mnew;
            al_sh[r] = a;
        }
        __syncthreads();

        // ---- O = O*alpha + P @ V ----
#pragma unroll
        for (int mt = 0; mt < 2; mt++) {
            const int r0 = pm * 32 + mt * 16 + g;
            const float a0 = al_sh[r0], a1 = al_sh[r0 + 8];
#pragma unroll
            for (int nt = 0; nt < 4; nt++) {
                oacc[mt][nt][0] *= a0; oacc[mt][nt][1] *= a0;
                oacc[mt][nt][2] *= a1; oacc[mt][nt][3] *= a1;
            }
        }
#pragma unroll
        for (int ks = 0; ks < 16; ks++) {
            uint32_t afr[2][4], bfr[4][2];
#pragma unroll
            for (int mt = 0; mt < 2; mt++) {
                const uint32_t* base = smem + PS_OFF + (pm * 32 + mt * 16 + g) * 132 + ks * 8 + t;
                afr[mt][0] = base[0];
                afr[mt][1] = base[8 * 132];
                afr[mt][2] = base[4];
                afr[mt][3] = base[8 * 132 + 4];
            }
#pragma unroll
            for (int nt = 0; nt < 4; nt++) {
                const uint32_t* base = smem + VS_OFF + (ks * 8 + t) * 72 + pn * 32 + nt * 8 + g;
                bfr[nt][0] = base[0];
                bfr[nt][1] = base[4 * 72];
            }
#pragma unroll
            for (int mt = 0; mt < 2; mt++)
#pragma unroll
                for (int nt = 0; nt < 4; nt++)
                    mma_tf32(oacc[mt][nt], afr[mt], bfr[nt]);
        }
    }
    __syncthreads();

    // normalize + write ctx [B,L,D]
#pragma unroll
    for (int mt = 0; mt < 2; mt++) {
        const int r0 = pm * 32 + mt * 16 + g;
        const int r1 = r0 + 8;
        const float inv0 = 1.0f / l_sh[r0];
        const float inv1 = 1.0f / l_sh[r1];
#pragma unroll
        for (int nt = 0; nt < 4; nt++) {
            const int c = pn * 32 + nt * 8 + 2 * t;
            float2 o0, o1;
            o0.x = oacc[mt][nt][0] * inv0; o0.y = oacc[mt][nt][1] * inv0;
            o1.x = oacc[mt][nt][2] * inv1; o1.y = oacc[mt][nt][3] * inv1;
            *(float2*)&ctx[((size_t)b * LL + q0 + r0) * DD + h * HDD + c] = o0;
            *(float2*)&ctx[((size_t)b * LL + q0 + r1) * DD + h * HDD + c] = o1;
        }
    }
}

// ---------------------------------------------------------------------------
extern "C" void kernel_launch(void* const* d_in, const int* in_sizes, int n_in,
                              void* d_out, int out_size)
{
    const float* hs   = (const float*)d_in[0];
    const float* mask = (const float*)d_in[1];
    const float* Wq = (const float*)d_in[2]; const float* bq = (const float*)d_in[3];
    const float* Wk = (const float*)d_in[4]; const float* bk = (const float*)d_in[5];
    const float* Wv = (const float*)d_in[6]; const float* bv = (const float*)d_in[7];
    const float* Wo = (const float*)d_in[8]; const float* bo = (const float*)d_in[9];
    float* out = (float*)d_out;

    cudaFuncSetAttribute(qkv_gemm_tc, cudaFuncAttributeMaxDynamicSharedMemorySize, GEMM_SMEM);
    cudaFuncSetAttribute(out_gemm_tc, cudaFuncAttributeMaxDynamicSharedMemorySize, GEMM_SMEM);
    cudaFuncSetAttribute(attn_tc, cudaFuncAttributeMaxDynamicSharedMemorySize, ATTN_SMEM);

    float* ctx_ptr = nullptr;
    cudaGetSymbolAddress((void**)&ctx_ptr, g_ctx);

    // 1) QKV projections
    dim3 ggrid(1024 / 128, 4096 / 128, 3);
    qkv_gemm_tc<<<ggrid, 256, GEMM_SMEM>>>(hs, Wq, bq, Wk, bk, Wv, bv);

    // 2) Attention
    dim3 agrid(LL / 128, BB * HH);
    attn_tc<<<agrid, 256, ATTN_SMEM>>>(mask, ctx_ptr);

    // 3) Output projection
    dim3 ogrid(1024 / 128, 4096 / 128, 1);
    out_gemm_tc<<<ogrid, 256, GEMM_SMEM>>>(Wo, bo, out);
}

// round 6
// speedup vs baseline: 2.6807x; 1.0000x over previous
#include <cuda_runtime.h>
#include <math.h>
#include <stdint.h>

// Problem constants
#define BB 2
#define LL 2048
#define DD 1024
#define HH 16
#define HDD 64
#define MTOT (BB*LL)   // 4096

// Scratch (allocation-free rule: __device__ globals)
__device__ float g_q[MTOT * DD];
__device__ float g_k[MTOT * DD];
__device__ float g_v[MTOT * DD];
__device__ float g_ctx[MTOT * DD];

// ---------------------------------------------------------------------------
// tf32 helpers
// ---------------------------------------------------------------------------
__device__ __forceinline__ uint32_t f2tf(float f) {
    uint32_t r;
    asm("cvt.rna.tf32.f32 %0, %1;" : "=r"(r) : "f"(f));
    return r;
}

__device__ __forceinline__ void mma_tf32(float* d, const uint32_t* a, const uint32_t* b) {
    asm volatile(
        "mma.sync.aligned.m16n8k8.row.col.f32.tf32.tf32.f32 "
        "{%0,%1,%2,%3}, {%4,%5,%6,%7}, {%8,%9}, {%0,%1,%2,%3};\n"
        : "+f"(d[0]), "+f"(d[1]), "+f"(d[2]), "+f"(d[3])
        : "r"(a[0]), "r"(a[1]), "r"(a[2]), "r"(a[3]), "r"(b[0]), "r"(b[1]));
}

// ---------------------------------------------------------------------------
// Tensor-core SGEMM (tf32): C[M=4096][N=1024] = A @ W + bias
// Block 128x128, BK=32, 8 warps (2x4), warp tile 64x32 (4x4 m16n8k8 tiles).
// As[m][k] stride 36; Bs[k][n] stride 136. Double-buffered.
// ---------------------------------------------------------------------------
#define G_ASTRIDE 36
#define G_BSTRIDE 136
#define G_ABUF (128 * G_ASTRIDE)      // 4608 words
#define G_BBUF (32 * G_BSTRIDE)       // 4352 words
#define G_BUF  (G_ABUF + G_BBUF)      // 8960 words
#define GEMM_SMEM (2 * G_BUF * 4)     // 71680 bytes

__device__ __forceinline__ void gemm_tc_body(const float* __restrict__ A,
                                             const float* __restrict__ W,
                                             const float* __restrict__ bias,
                                             float* __restrict__ C)
{
    extern __shared__ float smemf[];
    uint32_t* smem = (uint32_t*)smemf;

    const int tid  = threadIdx.x;
    const int warp = tid >> 5;
    const int lane = tid & 31;
    const int g    = lane >> 2;   // groupID
    const int t    = lane & 3;    // threadID in group
    const int wm   = warp >> 2;   // 0..1
    const int wn   = warp & 3;    // 0..3
    const int m0 = blockIdx.y * 128;
    const int n0 = blockIdx.x * 128;

    // staging-load index precompute
    const int am = ( (0*256 + tid) >> 3 );            // varies per i below
    (void)am;

    float acc[4][4][4];
#pragma unroll
    for (int mt = 0; mt < 4; mt++)
#pragma unroll
        for (int nt = 0; nt < 4; nt++)
#pragma unroll
            for (int c = 0; c < 4; c++) acc[mt][nt][c] = 0.0f;

    float4 ar[4], br[4];

    // prologue: load tile 0
#pragma unroll
    for (int i = 0; i < 4; i++) {
        int idx = i * 256 + tid;
        int m = idx >> 3, q = idx & 7;
        ar[i] = *(const float4*)&A[(size_t)(m0 + m) * 1024 + 4 * q];
        int k = idx >> 5, qn = idx & 31;
        br[i] = *(const float4*)&W[(size_t)k * 1024 + n0 + 4 * qn];
    }
    // store tile 0 -> buf0
#pragma unroll
    for (int i = 0; i < 4; i++) {
        int idx = i * 256 + tid;
        int m = idx >> 3, q = idx & 7;
        uint32_t* as = smem;  // buf0
        as[m * G_ASTRIDE + 4 * q + 0] = f2tf(ar[i].x);
        as[m * G_ASTRIDE + 4 * q + 1] = f2tf(ar[i].y);
        as[m * G_ASTRIDE + 4 * q + 2] = f2tf(ar[i].z);
        as[m * G_ASTRIDE + 4 * q + 3] = f2tf(ar[i].w);
        int k = idx >> 5, qn = idx & 31;
        uint32_t* bs = smem + G_ABUF;
        bs[k * G_BSTRIDE + 4 * qn + 0] = f2tf(br[i].x);
        bs[k * G_BSTRIDE + 4 * qn + 1] = f2tf(br[i].y);
        bs[k * G_BSTRIDE + 4 * qn + 2] = f2tf(br[i].z);
        bs[k * G_BSTRIDE + 4 * qn + 3] = f2tf(br[i].w);
    }
    __syncthreads();

#pragma unroll 1
    for (int kt = 0; kt < 32; kt++) {
        const int cur = kt & 1;
        const uint32_t* as = smem + cur * G_BUF;
        const uint32_t* bs = smem + cur * G_BUF + G_ABUF;

        if (kt < 31) {
            const int k0 = (kt + 1) * 32;
#pragma unroll
            for (int i = 0; i < 4; i++) {
                int idx = i * 256 + tid;
                int m = idx >> 3, q = idx & 7;
                ar[i] = *(const float4*)&A[(size_t)(m0 + m) * 1024 + k0 + 4 * q];
                int k = idx >> 5, qn = idx & 31;
                br[i] = *(const float4*)&W[(size_t)(k0 + k) * 1024 + n0 + 4 * qn];
            }
        }

#pragma unroll
        for (int ks = 0; ks < 4; ks++) {
            uint32_t afr[4][4], bfr[4][2];
#pragma unroll
            for (int mt = 0; mt < 4; mt++) {
                const uint32_t* base = as + (wm * 64 + mt * 16 + g) * G_ASTRIDE + ks * 8 + t;
                afr[mt][0] = base[0];
                afr[mt][1] = base[8 * G_ASTRIDE];
                afr[mt][2] = base[4];
                afr[mt][3] = base[8 * G_ASTRIDE + 4];
            }
#pragma unroll
            for (int nt = 0; nt < 4; nt++) {
                const uint32_t* base = bs + (ks * 8 + t) * G_BSTRIDE + wn * 32 + nt * 8 + g;
                bfr[nt][0] = base[0];
                bfr[nt][1] = base[4 * G_BSTRIDE];
            }
#pragma unroll
            for (int mt = 0; mt < 4; mt++)
#pragma unroll
                for (int nt = 0; nt < 4; nt++)
                    mma_tf32(acc[mt][nt], afr[mt], bfr[nt]);
        }

        if (kt < 31) {
            uint32_t* as2 = smem + (cur ^ 1) * G_BUF;
            uint32_t* bs2 = as2 + G_ABUF;
#pragma unroll
            for (int i = 0; i < 4; i++) {
                int idx = i * 256 + tid;
                int m = idx >> 3, q = idx & 7;
                as2[m * G_ASTRIDE + 4 * q + 0] = f2tf(ar[i].x);
                as2[m * G_ASTRIDE + 4 * q + 1] = f2tf(ar[i].y);
                as2[m * G_ASTRIDE + 4 * q + 2] = f2tf(ar[i].z);
                as2[m * G_ASTRIDE + 4 * q + 3] = f2tf(ar[i].w);
                int k = idx >> 5, qn = idx & 31;
                bs2[k * G_BSTRIDE + 4 * qn + 0] = f2tf(br[i].x);
                bs2[k * G_BSTRIDE + 4 * qn + 1] = f2tf(br[i].y);
                bs2[k * G_BSTRIDE + 4 * qn + 2] = f2tf(br[i].z);
                bs2[k * G_BSTRIDE + 4 * qn + 3] = f2tf(br[i].w);
            }
        }
        __syncthreads();
    }

    // epilogue: bias + store
#pragma unroll
    for (int mt = 0; mt < 4; mt++) {
        const int r0 = m0 + wm * 64 + mt * 16 + g;
        const int r1 = r0 + 8;
#pragma unroll
        for (int nt = 0; nt < 4; nt++) {
            const int c = n0 + wn * 32 + nt * 8 + 2 * t;
            const float b0 = bias[c], b1 = bias[c + 1];
            float2 o0, o1;
            o0.x = acc[mt][nt][0] + b0; o0.y = acc[mt][nt][1] + b1;
            o1.x = acc[mt][nt][2] + b0; o1.y = acc[mt][nt][3] + b1;
            *(float2*)&C[(size_t)r0 * 1024 + c] = o0;
            *(float2*)&C[(size_t)r1 * 1024 + c] = o1;
        }
    }
}

__global__ __launch_bounds__(256, 1) void qkv_gemm_tc(
    const float* __restrict__ A,
    const float* __restrict__ Wq, const float* __restrict__ bq,
    const float* __restrict__ Wk, const float* __restrict__ bk,
    const float* __restrict__ Wv, const float* __restrict__ bv)
{
    const float* W; const float* bias; float* C;
    if (blockIdx.z == 0)      { W = Wq; bias = bq; C = g_q; }
    else if (blockIdx.z == 1) { W = Wk; bias = bk; C = g_k; }
    else                      { W = Wv; bias = bv; C = g_v; }
    gemm_tc_body(A, W, bias, C);
}

__global__ __launch_bounds__(256, 1) void out_gemm_tc(
    const float* __restrict__ W, const float* __restrict__ bias,
    float* __restrict__ out)
{
    gemm_tc_body(g_ctx, W, bias, out);
}

// ---------------------------------------------------------------------------
// Flash attention with tf32 mma. q-tile=128, kv-tile=128, HD=64, 256 threads.
// S phase: warps 2x4 (tile 64x32).  PV phase: warps 4x2 (tile 32x32).
// smem (words): Qs[128*68] Ks[128*68] Vs[128*72] Ps[128*132] mask[128] m/l/al[128]
// ---------------------------------------------------------------------------
#define QS_OFF 0
#define KS_OFF 8704
#define VS_OFF 17408
#define PS_OFF 26624
#define MK_OFF 43520
#define M_OFF  43648
#define L_OFF  43776
#define AL_OFF 43904
#define ATTN_WORDS 44032
#define ATTN_SMEM (ATTN_WORDS * 4)

__global__ __launch_bounds__(256, 1) void attn_tc(const float* __restrict__ mask,
                                                  float* __restrict__ ctx)
{
    extern __shared__ float smemf[];
    uint32_t* smem = (uint32_t*)smemf;
    float* Qs = smemf + QS_OFF;     // [q][d]  stride 68
    float* Ks = smemf + KS_OFF;     // [kv][d] stride 68
    float* Vs = smemf + VS_OFF;     // [kv][d] stride 72
    float* Ps = smemf + PS_OFF;     // [q][kv] stride 132
    float* mk = smemf + MK_OFF;
    float* m_sh = smemf + M_OFF;
    float* l_sh = smemf + L_OFF;
    float* al_sh = smemf + AL_OFF;

    const int tid  = threadIdx.x;
    const int warp = tid >> 5;
    const int lane = tid & 31;
    const int g    = lane >> 2;
    const int t    = lane & 3;
    const int wm = warp >> 2, wn = warp & 3;   // S phase
    const int pm = warp >> 1, pn = warp & 1;   // PV phase

    const int b  = blockIdx.y / HH;
    const int h  = blockIdx.y % HH;
    const int q0 = blockIdx.x * 128;

    const float* qg = g_q + ((size_t)b * LL + q0) * DD + h * HDD;
    const float* kb = g_k + (size_t)b * LL * DD + h * HDD;
    const float* vb = g_v + (size_t)b * LL * DD + h * HDD;
    const float* mrow = mask + (size_t)b * LL;

    // Load Q (scaled, tf32)
#pragma unroll
    for (int i = 0; i < 8; i++) {
        int idx = i * 256 + tid;
        int r = idx >> 4, q4 = idx & 15;
        float4 v = *(const float4*)&qg[(size_t)r * DD + 4 * q4];
        uint32_t* dst = smem + QS_OFF + r * 68 + 4 * q4;
        dst[0] = f2tf(v.x * 0.125f);
        dst[1] = f2tf(v.y * 0.125f);
        dst[2] = f2tf(v.z * 0.125f);
        dst[3] = f2tf(v.w * 0.125f);
    }
    if (tid < 128) { m_sh[tid] = -INFINITY; l_sh[tid] = 0.0f; }

    float oacc[2][4][4];
#pragma unroll
    for (int mt = 0; mt < 2; mt++)
#pragma unroll
        for (int nt = 0; nt < 4; nt++)
#pragma unroll
            for (int c = 0; c < 4; c++) oacc[mt][nt][c] = 0.0f;

#pragma unroll 1
    for (int kt = 0; kt < LL / 128; kt++) {
        __syncthreads();   // previous PV done before overwriting Ks/Vs/Ps
        const float* kg = kb + (size_t)kt * 128 * DD;
        const float* vg = vb + (size_t)kt * 128 * DD;
#pragma unroll
        for (int i = 0; i < 8; i++) {
            int idx = i * 256 + tid;
            int r = idx >> 4, q4 = idx & 15;
            float4 kv4 = *(const float4*)&kg[(size_t)r * DD + 4 * q4];
            uint32_t* kd = smem + KS_OFF + r * 68 + 4 * q4;
            kd[0] = f2tf(kv4.x); kd[1] = f2tf(kv4.y);
            kd[2] = f2tf(kv4.z); kd[3] = f2tf(kv4.w);
            float4 vv4 = *(const float4*)&vg[(size_t)r * DD + 4 * q4];
            uint32_t* vd = smem + VS_OFF + r * 72 + 4 * q4;
            vd[0] = f2tf(vv4.x); vd[1] = f2tf(vv4.y);
            vd[2] = f2tf(vv4.z); vd[3] = f2tf(vv4.w);
        }
        if (tid < 128) mk[tid] = mrow[kt * 128 + tid];
        __syncthreads();

        // ---- S = Q @ K^T ----
        float sacc[4][4][4];
#pragma unroll
        for (int mt = 0; mt < 4; mt++)
#pragma unroll
            for (int nt = 0; nt < 4; nt++)
#pragma unroll
                for (int c = 0; c < 4; c++) sacc[mt][nt][c] = 0.0f;

#pragma unroll
        for (int ks = 0; ks < 8; ks++) {
            uint32_t afr[4][4], bfr[4][2];
#pragma unroll
            for (int mt = 0; mt < 4; mt++) {
                const uint32_t* base = smem + QS_OFF + (wm * 64 + mt * 16 + g) * 68 + ks * 8 + t;
                afr[mt][0] = base[0];
                afr[mt][1] = base[8 * 68];
                afr[mt][2] = base[4];
                afr[mt][3] = base[8 * 68 + 4];
            }
#pragma unroll
            for (int nt = 0; nt < 4; nt++) {
                const uint32_t* base = smem + KS_OFF + (wn * 32 + nt * 8 + g) * 68 + ks * 8 + t;
                bfr[nt][0] = base[0];
                bfr[nt][1] = base[4];
            }
#pragma unroll
            for (int mt = 0; mt < 4; mt++)
#pragma unroll
                for (int nt = 0; nt < 4; nt++)
                    mma_tf32(sacc[mt][nt], afr[mt], bfr[nt]);
        }

        // write S + mask to Ps
#pragma unroll
        for (int mt = 0; mt < 4; mt++) {
            const int r0 = wm * 64 + mt * 16 + g;
#pragma unroll
            for (int nt = 0; nt < 4; nt++) {
                const int c = wn * 32 + nt * 8 + 2 * t;
                const float mk0 = mk[c], mk1 = mk[c + 1];
                float2 s0, s1;
                s0.x = sacc[mt][nt][0] + mk0; s0.y = sacc[mt][nt][1] + mk1;
                s1.x = sacc[mt][nt][2] + mk0; s1.y = sacc[mt][nt][3] + mk1;
                *(float2*)&Ps[r0 * 132 + c]       = s0;
                *(float2*)&Ps[(r0 + 8) * 132 + c] = s1;
            }
        }
        __syncthreads();

        // ---- online softmax: 2 lanes per row ----
        {
            const int r = tid >> 1, half = tid & 1;
            float* prow = &Ps[r * 132 + half * 64];
            float mx = -INFINITY;
#pragma unroll
            for (int i = 0; i < 16; i++) {
                float4 v = *(const float4*)&prow[i * 4];
                mx = fmaxf(mx, fmaxf(fmaxf(v.x, v.y), fmaxf(v.z, v.w)));
            }
            mx = fmaxf(mx, __shfl_xor_sync(0xFFFFFFFF, mx, 1));
            const float mold = m_sh[r];
            const float mnew = fmaxf(mold, mx);
            const float a = __expf(mold - mnew);
            float ssum = 0.0f;
            uint32_t* prowu = (uint32_t*)prow;
#pragma unroll
            for (int i = 0; i < 16; i++) {
                float4 v = *(const float4*)&prow[i * 4];
                float p0 = __expf(v.x - mnew);
                float p1 = __expf(v.y - mnew);
                float p2 = __expf(v.z - mnew);
                float p3 = __expf(v.w - mnew);
                ssum += (p0 + p1) + (p2 + p3);
                prowu[i * 4 + 0] = f2tf(p0);
                prowu[i * 4 + 1] = f2tf(p1);
                prowu[i * 4 + 2] = f2tf(p2);
                prowu[i * 4 + 3] = f2tf(p3);
            }
            ssum += __shfl_xor_sync(0xFFFFFFFF, ssum, 1);
            l_sh[r] = l_sh[r] * a + ssum;
            m_sh[r] = mnew;
            al_sh[r] = a;
        }
        __syncthreads();

        // ---- O = O*alpha + P @ V ----
#pragma unroll
        for (int mt = 0; mt < 2; mt++) {
            const int r0 = pm * 32 + mt * 16 + g;
            const float a0 = al_sh[r0], a1 = al_sh[r0 + 8];
#pragma unroll
            for (int nt = 0; nt < 4; nt++) {
                oacc[mt][nt][0] *= a0; oacc[mt][nt][1] *= a0;
                oacc[mt][nt][2] *= a1; oacc[mt][nt][3] *= a1;
            }
        }
#pragma unroll
        for (int ks = 0; ks < 16; ks++) {
            uint32_t afr[2][4], bfr[4][2];
#pragma unroll
            for (int mt = 0; mt < 2; mt++) {
                const uint32_t* base = smem + PS_OFF + (pm * 32 + mt * 16 + g) * 132 + ks * 8 + t;
                afr[mt][0] = base[0];
                afr[mt][1] = base[8 * 132];
                afr[mt][2] = base[4];
                afr[mt][3] = base[8 * 132 + 4];
            }
#pragma unroll
            for (int nt = 0; nt < 4; nt++) {
                const uint32_t* base = smem + VS_OFF + (ks * 8 + t) * 72 + pn * 32 + nt * 8 + g;
                bfr[nt][0] = base[0];
                bfr[nt][1] = base[4 * 72];
            }
#pragma unroll
            for (int mt = 0; mt < 2; mt++)
#pragma unroll
                for (int nt = 0; nt < 4; nt++)
                    mma_tf32(oacc[mt][nt], afr[mt], bfr[nt]);
        }
    }
    __syncthreads();

    // normalize + write ctx [B,L,D]
#pragma unroll
    for (int mt = 0; mt < 2; mt++) {
        const int r0 = pm * 32 + mt * 16 + g;
        const int r1 = r0 + 8;
        const float inv0 = 1.0f / l_sh[r0];
        const float inv1 = 1.0f / l_sh[r1];
#pragma unroll
        for (int nt = 0; nt < 4; nt++) {
            const int c = pn * 32 + nt * 8 + 2 * t;
            float2 o0, o1;
            o0.x = oacc[mt][nt][0] * inv0; o0.y = oacc[mt][nt][1] * inv0;
            o1.x = oacc[mt][nt][2] * inv1; o1.y = oacc[mt][nt][3] * inv1;
            *(float2*)&ctx[((size_t)b * LL + q0 + r0) * DD + h * HDD + c] = o0;
            *(float2*)&ctx[((size_t)b * LL + q0 + r1) * DD + h * HDD + c] = o1;
        }
    }
}

// ---------------------------------------------------------------------------
extern "C" void kernel_launch(void* const* d_in, const int* in_sizes, int n_in,
                              void* d_out, int out_size)
{
    const float* hs   = (const float*)d_in[0];
    const float* mask = (const float*)d_in[1];
    const float* Wq = (const float*)d_in[2]; const float* bq = (const float*)d_in[3];
    const float* Wk = (const float*)d_in[4]; const float* bk = (const float*)d_in[5];
    const float* Wv = (const float*)d_in[6]; const float* bv = (const float*)d_in[7];
    const float* Wo = (const float*)d_in[8]; const float* bo = (const float*)d_in[9];
    float* out = (float*)d_out;

    cudaFuncSetAttribute(qkv_gemm_tc, cudaFuncAttributeMaxDynamicSharedMemorySize, GEMM_SMEM);
    cudaFuncSetAttribute(out_gemm_tc, cudaFuncAttributeMaxDynamicSharedMemorySize, GEMM_SMEM);
    cudaFuncSetAttribute(attn_tc, cudaFuncAttributeMaxDynamicSharedMemorySize, ATTN_SMEM);

    float* ctx_ptr = nullptr;
    cudaGetSymbolAddress((void**)&ctx_ptr, g_ctx);

    // 1) QKV projections
    dim3 ggrid(1024 / 128, 4096 / 128, 3);
    qkv_gemm_tc<<<ggrid, 256, GEMM_SMEM>>>(hs, Wq, bq, Wk, bk, Wv, bv);

    // 2) Attention
    dim3 agrid(LL / 128, BB * HH);
    attn_tc<<<agrid, 256, ATTN_SMEM>>>(mask, ctx_ptr);

    // 3) Output projection
    dim3 ogrid(1024 / 128, 4096 / 128, 1);
    out_gemm_tc<<<ogrid, 256, GEMM_SMEM>>>(Wo, bo, out);
}

// round 7
// speedup vs baseline: 2.6863x; 1.0021x over previous
#include <cuda_runtime.h>
#include <math.h>
#include <stdint.h>

// Problem constants
#define BB 2
#define LL 2048
#define DD 1024
#define HH 16
#define HDD 64
#define MTOT (BB*LL)   // 4096

// Scratch (allocation-free rule: __device__ globals)
__device__ float g_q[MTOT * DD];
__device__ float g_k[MTOT * DD];
__device__ float g_v[MTOT * DD];
__device__ float g_ctx[MTOT * DD];

// ---------------------------------------------------------------------------
// tf32 helpers
// ---------------------------------------------------------------------------
__device__ __forceinline__ uint32_t f2tf(float f) {
    uint32_t r;
    asm("cvt.rna.tf32.f32 %0, %1;" : "=r"(r) : "f"(f));
    return r;
}

__device__ __forceinline__ void mma_tf32(float* d, const uint32_t* a, const uint32_t* b) {
    asm volatile(
        "mma.sync.aligned.m16n8k8.row.col.f32.tf32.tf32.f32 "
        "{%0,%1,%2,%3}, {%4,%5,%6,%7}, {%8,%9}, {%0,%1,%2,%3};\n"
        : "+f"(d[0]), "+f"(d[1]), "+f"(d[2]), "+f"(d[3])
        : "r"(a[0]), "r"(a[1]), "r"(a[2]), "r"(a[3]), "r"(b[0]), "r"(b[1]));
}

// ---------------------------------------------------------------------------
// Tensor-core SGEMM (tf32): C[M=4096][N=1024] = A @ W + bias
// Block 128x128, BK=32, 8 warps (2x4), warp tile 64x32 (4x4 m16n8k8 tiles).
// As[m][k] stride 36; Bs[k][n] stride 136. Double-buffered.
// ---------------------------------------------------------------------------
#define G_ASTRIDE 36
#define G_BSTRIDE 136
#define G_ABUF (128 * G_ASTRIDE)      // 4608 words
#define G_BBUF (32 * G_BSTRIDE)       // 4352 words
#define G_BUF  (G_ABUF + G_BBUF)      // 8960 words
#define GEMM_SMEM (2 * G_BUF * 4)     // 71680 bytes

__device__ __forceinline__ void gemm_tc_body(const float* __restrict__ A,
                                             const float* __restrict__ W,
                                             const float* __restrict__ bias,
                                             float* __restrict__ C)
{
    extern __shared__ float smemf[];
    uint32_t* smem = (uint32_t*)smemf;

    const int tid  = threadIdx.x;
    const int warp = tid >> 5;
    const int lane = tid & 31;
    const int g    = lane >> 2;   // groupID
    const int t    = lane & 3;    // threadID in group
    const int wm   = warp >> 2;   // 0..1
    const int wn   = warp & 3;    // 0..3
    const int m0 = blockIdx.y * 128;
    const int n0 = blockIdx.x * 128;

    // staging-load index precompute
    const int am = ( (0*256 + tid) >> 3 );            // varies per i below
    (void)am;

    float acc[4][4][4];
#pragma unroll
    for (int mt = 0; mt < 4; mt++)
#pragma unroll
        for (int nt = 0; nt < 4; nt++)
#pragma unroll
            for (int c = 0; c < 4; c++) acc[mt][nt][c] = 0.0f;

    float4 ar[4], br[4];

    // prologue: load tile 0
#pragma unroll
    for (int i = 0; i < 4; i++) {
        int idx = i * 256 + tid;
        int m = idx >> 3, q = idx & 7;
        ar[i] = *(const float4*)&A[(size_t)(m0 + m) * 1024 + 4 * q];
        int k = idx >> 5, qn = idx & 31;
        br[i] = *(const float4*)&W[(size_t)k * 1024 + n0 + 4 * qn];
    }
    // store tile 0 -> buf0
#pragma unroll
    for (int i = 0; i < 4; i++) {
        int idx = i * 256 + tid;
        int m = idx >> 3, q = idx & 7;
        uint32_t* as = smem;  // buf0
        as[m * G_ASTRIDE + 4 * q + 0] = f2tf(ar[i].x);
        as[m * G_ASTRIDE + 4 * q + 1] = f2tf(ar[i].y);
        as[m * G_ASTRIDE + 4 * q + 2] = f2tf(ar[i].z);
        as[m * G_ASTRIDE + 4 * q + 3] = f2tf(ar[i].w);
        int k = idx >> 5, qn = idx & 31;
        uint32_t* bs = smem + G_ABUF;
        bs[k * G_BSTRIDE + 4 * qn + 0] = f2tf(br[i].x);
        bs[k * G_BSTRIDE + 4 * qn + 1] = f2tf(br[i].y);
        bs[k * G_BSTRIDE + 4 * qn + 2] = f2tf(br[i].z);
        bs[k * G_BSTRIDE + 4 * qn + 3] = f2tf(br[i].w);
    }
    __syncthreads();

#pragma unroll 1
    for (int kt = 0; kt < 32; kt++) {
        const int cur = kt & 1;
        const uint32_t* as = smem + cur * G_BUF;
        const uint32_t* bs = smem + cur * G_BUF + G_ABUF;

        if (kt < 31) {
            const int k0 = (kt + 1) * 32;
#pragma unroll
            for (int i = 0; i < 4; i++) {
                int idx = i * 256 + tid;
                int m = idx >> 3, q = idx & 7;
                ar[i] = *(const float4*)&A[(size_t)(m0 + m) * 1024 + k0 + 4 * q];
                int k = idx >> 5, qn = idx & 31;
                br[i] = *(const float4*)&W[(size_t)(k0 + k) * 1024 + n0 + 4 * qn];
            }
        }

#pragma unroll
        for (int ks = 0; ks < 4; ks++) {
            uint32_t afr[4][4], bfr[4][2];
#pragma unroll
            for (int mt = 0; mt < 4; mt++) {
                const uint32_t* base = as + (wm * 64 + mt * 16 + g) * G_ASTRIDE + ks * 8 + t;
                afr[mt][0] = base[0];
                afr[mt][1] = base[8 * G_ASTRIDE];
                afr[mt][2] = base[4];
                afr[mt][3] = base[8 * G_ASTRIDE + 4];
            }
#pragma unroll
            for (int nt = 0; nt < 4; nt++) {
                const uint32_t* base = bs + (ks * 8 + t) * G_BSTRIDE + wn * 32 + nt * 8 + g;
                bfr[nt][0] = base[0];
                bfr[nt][1] = base[4 * G_BSTRIDE];
            }
#pragma unroll
            for (int mt = 0; mt < 4; mt++)
#pragma unroll
                for (int nt = 0; nt < 4; nt++)
                    mma_tf32(acc[mt][nt], afr[mt], bfr[nt]);
        }

        if (kt < 31) {
            uint32_t* as2 = smem + (cur ^ 1) * G_BUF;
            uint32_t* bs2 = as2 + G_ABUF;
#pragma unroll
            for (int i = 0; i < 4; i++) {
                int idx = i * 256 + tid;
                int m = idx >> 3, q = idx & 7;
                as2[m * G_ASTRIDE + 4 * q + 0] = f2tf(ar[i].x);
                as2[m * G_ASTRIDE + 4 * q + 1] = f2tf(ar[i].y);
                as2[m * G_ASTRIDE + 4 * q + 2] = f2tf(ar[i].z);
                as2[m * G_ASTRIDE + 4 * q + 3] = f2tf(ar[i].w);
                int k = idx >> 5, qn = idx & 31;
                bs2[k * G_BSTRIDE + 4 * qn + 0] = f2tf(br[i].x);
                bs2[k * G_BSTRIDE + 4 * qn + 1] = f2tf(br[i].y);
                bs2[k * G_BSTRIDE + 4 * qn + 2] = f2tf(br[i].z);
                bs2[k * G_BSTRIDE + 4 * qn + 3] = f2tf(br[i].w);
            }
        }
        __syncthreads();
    }

    // epilogue: bias + store
#pragma unroll
    for (int mt = 0; mt < 4; mt++) {
        const int r0 = m0 + wm * 64 + mt * 16 + g;
        const int r1 = r0 + 8;
#pragma unroll
        for (int nt = 0; nt < 4; nt++) {
            const int c = n0 + wn * 32 + nt * 8 + 2 * t;
            const float b0 = bias[c], b1 = bias[c + 1];
            float2 o0, o1;
            o0.x = acc[mt][nt][0] + b0; o0.y = acc[mt][nt][1] + b1;
            o1.x = acc[mt][nt][2] + b0; o1.y = acc[mt][nt][3] + b1;
            *(float2*)&C[(size_t)r0 * 1024 + c] = o0;
            *(float2*)&C[(size_t)r1 * 1024 + c] = o1;
        }
    }
}

__global__ __launch_bounds__(256, 1) void qkv_gemm_tc(
    const float* __restrict__ A,
    const float* __restrict__ Wq, const float* __restrict__ bq,
    const float* __restrict__ Wk, const float* __restrict__ bk,
    const float* __restrict__ Wv, const float* __restrict__ bv)
{
    const float* W; const float* bias; float* C;
    if (blockIdx.z == 0)      { W = Wq; bias = bq; C = g_q; }
    else if (blockIdx.z == 1) { W = Wk; bias = bk; C = g_k; }
    else                      { W = Wv; bias = bv; C = g_v; }
    gemm_tc_body(A, W, bias, C);
}

__global__ __launch_bounds__(256, 1) void out_gemm_tc(
    const float* __restrict__ W, const float* __restrict__ bias,
    float* __restrict__ out)
{
    gemm_tc_body(g_ctx, W, bias, out);
}

// ---------------------------------------------------------------------------
// Flash attention with tf32 mma. q-tile=128, kv-tile=128, HD=64, 256 threads.
// S phase: warps 2x4 (tile 64x32).  PV phase: warps 4x2 (tile 32x32).
// smem (words): Qs[128*68] Ks[128*68] Vs[128*72] Ps[128*132] mask[128] m/l/al[128]
// ---------------------------------------------------------------------------
#define QS_OFF 0
#define KS_OFF 8704
#define VS_OFF 17408
#define PS_OFF 26624
#define MK_OFF 43520
#define M_OFF  43648
#define L_OFF  43776
#define AL_OFF 43904
#define ATTN_WORDS 44032
#define ATTN_SMEM (ATTN_WORDS * 4)

__global__ __launch_bounds__(256, 1) void attn_tc(const float* __restrict__ mask,
                                                  float* __restrict__ ctx)
{
    extern __shared__ float smemf[];
    uint32_t* smem = (uint32_t*)smemf;
    float* Qs = smemf + QS_OFF;     // [q][d]  stride 68
    float* Ks = smemf + KS_OFF;     // [kv][d] stride 68
    float* Vs = smemf + VS_OFF;     // [kv][d] stride 72
    float* Ps = smemf + PS_OFF;     // [q][kv] stride 132
    float* mk = smemf + MK_OFF;
    float* m_sh = smemf + M_OFF;
    float* l_sh = smemf + L_OFF;
    float* al_sh = smemf + AL_OFF;

    const int tid  = threadIdx.x;
    const int warp = tid >> 5;
    const int lane = tid & 31;
    const int g    = lane >> 2;
    const int t    = lane & 3;
    const int wm = warp >> 2, wn = warp & 3;   // S phase
    const int pm = warp >> 1, pn = warp & 1;   // PV phase

    const int b  = blockIdx.y / HH;
    const int h  = blockIdx.y % HH;
    const int q0 = blockIdx.x * 128;

    const float* qg = g_q + ((size_t)b * LL + q0) * DD + h * HDD;
    const float* kb = g_k + (size_t)b * LL * DD + h * HDD;
    const float* vb = g_v + (size_t)b * LL * DD + h * HDD;
    const float* mrow = mask + (size_t)b * LL;

    // Load Q (scaled, tf32)
#pragma unroll
    for (int i = 0; i < 8; i++) {
        int idx = i * 256 + tid;
        int r = idx >> 4, q4 = idx & 15;
        float4 v = *(const float4*)&qg[(size_t)r * DD + 4 * q4];
        uint32_t* dst = smem + QS_OFF + r * 68 + 4 * q4;
        dst[0] = f2tf(v.x * 0.125f);
        dst[1] = f2tf(v.y * 0.125f);
        dst[2] = f2tf(v.z * 0.125f);
        dst[3] = f2tf(v.w * 0.125f);
    }
    if (tid < 128) { m_sh[tid] = -INFINITY; l_sh[tid] = 0.0f; }

    float oacc[2][4][4];
#pragma unroll
    for (int mt = 0; mt < 2; mt++)
#pragma unroll
        for (int nt = 0; nt < 4; nt++)
#pragma unroll
            for (int c = 0; c < 4; c++) oacc[mt][nt][c] = 0.0f;

#pragma unroll 1
    for (int kt = 0; kt < LL / 128; kt++) {
        __syncthreads();   // previous PV done before overwriting Ks/Vs/Ps
        const float* kg = kb + (size_t)kt * 128 * DD;
        const float* vg = vb + (size_t)kt * 128 * DD;
#pragma unroll
        for (int i = 0; i < 8; i++) {
            int idx = i * 256 + tid;
            int r = idx >> 4, q4 = idx & 15;
            float4 kv4 = *(const float4*)&kg[(size_t)r * DD + 4 * q4];
            uint32_t* kd = smem + KS_OFF + r * 68 + 4 * q4;
            kd[0] = f2tf(kv4.x); kd[1] = f2tf(kv4.y);
            kd[2] = f2tf(kv4.z); kd[3] = f2tf(kv4.w);
            float4 vv4 = *(const float4*)&vg[(size_t)r * DD + 4 * q4];
            uint32_t* vd = smem + VS_OFF + r * 72 + 4 * q4;
            vd[0] = f2tf(vv4.x); vd[1] = f2tf(vv4.y);
            vd[2] = f2tf(vv4.z); vd[3] = f2tf(vv4.w);
        }
        if (tid < 128) mk[tid] = mrow[kt * 128 + tid];
        __syncthreads();

        // ---- S = Q @ K^T ----
        float sacc[4][4][4];
#pragma unroll
        for (int mt = 0; mt < 4; mt++)
#pragma unroll
            for (int nt = 0; nt < 4; nt++)
#pragma unroll
                for (int c = 0; c < 4; c++) sacc[mt][nt][c] = 0.0f;

#pragma unroll
        for (int ks = 0; ks < 8; ks++) {
            uint32_t afr[4][4], bfr[4][2];
#pragma unroll
            for (int mt = 0; mt < 4; mt++) {
                const uint32_t* base = smem + QS_OFF + (wm * 64 + mt * 16 + g) * 68 + ks * 8 + t;
                afr[mt][0] = base[0];
                afr[mt][1] = base[8 * 68];
                afr[mt][2] = base[4];
                afr[mt][3] = base[8 * 68 + 4];
            }
#pragma unroll
            for (int nt = 0; nt < 4; nt++) {
                const uint32_t* base = smem + KS_OFF + (wn * 32 + nt * 8 + g) * 68 + ks * 8 + t;
                bfr[nt][0] = base[0];
                bfr[nt][1] = base[4];
            }
#pragma unroll
            for (int mt = 0; mt < 4; mt++)
#pragma unroll
                for (int nt = 0; nt < 4; nt++)
                    mma_tf32(sacc[mt][nt], afr[mt], bfr[nt]);
        }

        // write S + mask to Ps
#pragma unroll
        for (int mt = 0; mt < 4; mt++) {
            const int r0 = wm * 64 + mt * 16 + g;
#pragma unroll
            for (int nt = 0; nt < 4; nt++) {
                const int c = wn * 32 + nt * 8 + 2 * t;
                const float mk0 = mk[c], mk1 = mk[c + 1];
                float2 s0, s1;
                s0.x = sacc[mt][nt][0] + mk0; s0.y = sacc[mt][nt][1] + mk1;
                s1.x = sacc[mt][nt][2] + mk0; s1.y = sacc[mt][nt][3] + mk1;
                *(float2*)&Ps[r0 * 132 + c]       = s0;
                *(float2*)&Ps[(r0 + 8) * 132 + c] = s1;
            }
        }
        __syncthreads();

        // ---- online softmax: 2 lanes per row ----
        {
            const int r = tid >> 1, half = tid & 1;
            float* prow = &Ps[r * 132 + half * 64];
            float mx = -INFINITY;
#pragma unroll
            for (int i = 0; i < 16; i++) {
                float4 v = *(const float4*)&prow[i * 4];
                mx = fmaxf(mx, fmaxf(fmaxf(v.x, v.y), fmaxf(v.z, v.w)));
            }
            mx = fmaxf(mx, __shfl_xor_sync(0xFFFFFFFF, mx, 1));
            const float mold = m_sh[r];
            const float mnew = fmaxf(mold, mx);
            const float a = __expf(mold - mnew);
            float ssum = 0.0f;
            uint32_t* prowu = (uint32_t*)prow;
#pragma unroll
            for (int i = 0; i < 16; i++) {
                float4 v = *(const float4*)&prow[i * 4];
                float p0 = __expf(v.x - mnew);
                float p1 = __expf(v.y - mnew);
                float p2 = __expf(v.z - mnew);
                float p3 = __expf(v.w - mnew);
                ssum += (p0 + p1) + (p2 + p3);
                prowu[i * 4 + 0] = f2tf(p0);
                prowu[i * 4 + 1] = f2tf(p1);
                prowu[i * 4 + 2] = f2tf(p2);
                prowu[i * 4 + 3] = f2tf(p3);
            }
            ssum += __shfl_xor_sync(0xFFFFFFFF, ssum, 1);
            l_sh[r] = l_sh[r] * a + ssum;
            m_sh[r] = mnew;
            al_sh[r] = a;
        }
        __syncthreads();

        // ---- O = O*alpha + P @ V ----
#pragma unroll
        for (int mt = 0; mt < 2; mt++) {
            const int r0 = pm * 32 + mt * 16 + g;
            const float a0 = al_sh[r0], a1 = al_sh[r0 + 8];
#pragma unroll
            for (int nt = 0; nt < 4; nt++) {
                oacc[mt][nt][0] *= a0; oacc[mt][nt][1] *= a0;
                oacc[mt][nt][2] *= a1; oacc[mt][nt][3] *= a1;
            }
        }
#pragma unroll
        for (int ks = 0; ks < 16; ks++) {
            uint32_t afr[2][4], bfr[4][2];
#pragma unroll
            for (int mt = 0; mt < 2; mt++) {
                const uint32_t* base = smem + PS_OFF + (pm * 32 + mt * 16 + g) * 132 + ks * 8 + t;
                afr[mt][0] = base[0];
                afr[mt][1] = base[8 * 132];
                afr[mt][2] = base[4];
                afr[mt][3] = base[8 * 132 + 4];
            }
#pragma unroll
            for (int nt = 0; nt < 4; nt++) {
                const uint32_t* base = smem + VS_OFF + (ks * 8 + t) * 72 + pn * 32 + nt * 8 + g;
                bfr[nt][0] = base[0];
                bfr[nt][1] = base[4 * 72];
            }
#pragma unroll
            for (int mt = 0; mt < 2; mt++)
#pragma unroll
                for (int nt = 0; nt < 4; nt++)
                    mma_tf32(oacc[mt][nt], afr[mt], bfr[nt]);
        }
    }
    __syncthreads();

    // normalize + write ctx [B,L,D]
#pragma unroll
    for (int mt = 0; mt < 2; mt++) {
        const int r0 = pm * 32 + mt * 16 + g;
        const int r1 = r0 + 8;
        const float inv0 = 1.0f / l_sh[r0];
        const float inv1 = 1.0f / l_sh[r1];
#pragma unroll
        for (int nt = 0; nt < 4; nt++) {
            const int c = pn * 32 + nt * 8 + 2 * t;
            float2 o0, o1;
            o0.x = oacc[mt][nt][0] * inv0; o0.y = oacc[mt][nt][1] * inv0;
            o1.x = oacc[mt][nt][2] * inv1; o1.y = oacc[mt][nt][3] * inv1;
            *(float2*)&ctx[((size_t)b * LL + q0 + r0) * DD + h * HDD + c] = o0;
            *(float2*)&ctx[((size_t)b * LL + q0 + r1) * DD + h * HDD + c] = o1;
        }
    }
}

// ---------------------------------------------------------------------------
extern "C" void kernel_launch(void* const* d_in, const int* in_sizes, int n_in,
                              void* d_out, int out_size)
{
    const float* hs   = (const float*)d_in[0];
    const float* mask = (const float*)d_in[1];
    const float* Wq = (const float*)d_in[2]; const float* bq = (const float*)d_in[3];
    const float* Wk = (const float*)d_in[4]; const float* bk = (const float*)d_in[5];
    const float* Wv = (const float*)d_in[6]; const float* bv = (const float*)d_in[7];
    const float* Wo = (const float*)d_in[8]; const float* bo = (const float*)d_in[9];
    float* out = (float*)d_out;

    cudaFuncSetAttribute(qkv_gemm_tc, cudaFuncAttributeMaxDynamicSharedMemorySize, GEMM_SMEM);
    cudaFuncSetAttribute(out_gemm_tc, cudaFuncAttributeMaxDynamicSharedMemorySize, GEMM_SMEM);
    cudaFuncSetAttribute(attn_tc, cudaFuncAttributeMaxDynamicSharedMemorySize, ATTN_SMEM);

    float* ctx_ptr = nullptr;
    cudaGetSymbolAddress((void**)&ctx_ptr, g_ctx);

    // 1) QKV projections
    dim3 ggrid(1024 / 128, 4096 / 128, 3);
    qkv_gemm_tc<<<ggrid, 256, GEMM_SMEM>>>(hs, Wq, bq, Wk, bk, Wv, bv);

    // 2) Attention
    dim3 agrid(LL / 128, BB * HH);
    attn_tc<<<agrid, 256, ATTN_SMEM>>>(mask, ctx_ptr);

    // 3) Output projection
    dim3 ogrid(1024 / 128, 4096 / 128, 1);
    out_gemm_tc<<<ogrid, 256, GEMM_SMEM>>>(Wo, bo, out);
}

// round 8
// speedup vs baseline: 2.6890x; 1.0010x over previous
#include <cuda_runtime.h>
#include <math.h>
#include <stdint.h>

// Problem constants
#define BB 2
#define LL 2048
#define DD 1024
#define HH 16
#define HDD 64
#define MTOT (BB*LL)   // 4096

// Scratch (allocation-free rule: __device__ globals)
__device__ float g_q[MTOT * DD];
__device__ float g_k[MTOT * DD];
__device__ float g_v[MTOT * DD];
__device__ float g_ctx[MTOT * DD];

// ---------------------------------------------------------------------------
// tf32 helpers
// ---------------------------------------------------------------------------
__device__ __forceinline__ uint32_t f2tf(float f) {
    uint32_t r;
    asm("cvt.rna.tf32.f32 %0, %1;" : "=r"(r) : "f"(f));
    return r;
}

__device__ __forceinline__ void mma_tf32(float* d, const uint32_t* a, const uint32_t* b) {
    asm volatile(
        "mma.sync.aligned.m16n8k8.row.col.f32.tf32.tf32.f32 "
        "{%0,%1,%2,%3}, {%4,%5,%6,%7}, {%8,%9}, {%0,%1,%2,%3};\n"
        : "+f"(d[0]), "+f"(d[1]), "+f"(d[2]), "+f"(d[3])
        : "r"(a[0]), "r"(a[1]), "r"(a[2]), "r"(a[3]), "r"(b[0]), "r"(b[1]));
}

// ---------------------------------------------------------------------------
// Tensor-core SGEMM (tf32): C[M=4096][N=1024] = A @ W + bias
// Block 128x128, BK=32, 8 warps (2x4), warp tile 64x32 (4x4 m16n8k8 tiles).
// As[m][k] stride 36; Bs[k][n] stride 136. Double-buffered.
// ---------------------------------------------------------------------------
#define G_ASTRIDE 36
#define G_BSTRIDE 136
#define G_ABUF (128 * G_ASTRIDE)      // 4608 words
#define G_BBUF (32 * G_BSTRIDE)       // 4352 words
#define G_BUF  (G_ABUF + G_BBUF)      // 8960 words
#define GEMM_SMEM (2 * G_BUF * 4)     // 71680 bytes

__device__ __forceinline__ void gemm_tc_body(const float* __restrict__ A,
                                             const float* __restrict__ W,
                                             const float* __restrict__ bias,
                                             float* __restrict__ C)
{
    extern __shared__ float smemf[];
    uint32_t* smem = (uint32_t*)smemf;

    const int tid  = threadIdx.x;
    const int warp = tid >> 5;
    const int lane = tid & 31;
    const int g    = lane >> 2;   // groupID
    const int t    = lane & 3;    // threadID in group
    const int wm   = warp >> 2;   // 0..1
    const int wn   = warp & 3;    // 0..3
    const int m0 = blockIdx.y * 128;
    const int n0 = blockIdx.x * 128;

    // staging-load index precompute
    const int am = ( (0*256 + tid) >> 3 );            // varies per i below
    (void)am;

    float acc[4][4][4];
#pragma unroll
    for (int mt = 0; mt < 4; mt++)
#pragma unroll
        for (int nt = 0; nt < 4; nt++)
#pragma unroll
            for (int c = 0; c < 4; c++) acc[mt][nt][c] = 0.0f;

    float4 ar[4], br[4];

    // prologue: load tile 0
#pragma unroll
    for (int i = 0; i < 4; i++) {
        int idx = i * 256 + tid;
        int m = idx >> 3, q = idx & 7;
        ar[i] = *(const float4*)&A[(size_t)(m0 + m) * 1024 + 4 * q];
        int k = idx >> 5, qn = idx & 31;
        br[i] = *(const float4*)&W[(size_t)k * 1024 + n0 + 4 * qn];
    }
    // store tile 0 -> buf0
#pragma unroll
    for (int i = 0; i < 4; i++) {
        int idx = i * 256 + tid;
        int m = idx >> 3, q = idx & 7;
        uint32_t* as = smem;  // buf0
        as[m * G_ASTRIDE + 4 * q + 0] = f2tf(ar[i].x);
        as[m * G_ASTRIDE + 4 * q + 1] = f2tf(ar[i].y);
        as[m * G_ASTRIDE + 4 * q + 2] = f2tf(ar[i].z);
        as[m * G_ASTRIDE + 4 * q + 3] = f2tf(ar[i].w);
        int k = idx >> 5, qn = idx & 31;
        uint32_t* bs = smem + G_ABUF;
        bs[k * G_BSTRIDE + 4 * qn + 0] = f2tf(br[i].x);
        bs[k * G_BSTRIDE + 4 * qn + 1] = f2tf(br[i].y);
        bs[k * G_BSTRIDE + 4 * qn + 2] = f2tf(br[i].z);
        bs[k * G_BSTRIDE + 4 * qn + 3] = f2tf(br[i].w);
    }
    __syncthreads();

#pragma unroll 1
    for (int kt = 0; kt < 32; kt++) {
        const int cur = kt & 1;
        const uint32_t* as = smem + cur * G_BUF;
        const uint32_t* bs = smem + cur * G_BUF + G_ABUF;

        if (kt < 31) {
            const int k0 = (kt + 1) * 32;
#pragma unroll
            for (int i = 0; i < 4; i++) {
                int idx = i * 256 + tid;
                int m = idx >> 3, q = idx & 7;
                ar[i] = *(const float4*)&A[(size_t)(m0 + m) * 1024 + k0 + 4 * q];
                int k = idx >> 5, qn = idx & 31;
                br[i] = *(const float4*)&W[(size_t)(k0 + k) * 1024 + n0 + 4 * qn];
            }
        }

#pragma unroll
        for (int ks = 0; ks < 4; ks++) {
            uint32_t afr[4][4], bfr[4][2];
#pragma unroll
            for (int mt = 0; mt < 4; mt++) {
                const uint32_t* base = as + (wm * 64 + mt * 16 + g) * G_ASTRIDE + ks * 8 + t;
                afr[mt][0] = base[0];
                afr[mt][1] = base[8 * G_ASTRIDE];
                afr[mt][2] = base[4];
                afr[mt][3] = base[8 * G_ASTRIDE + 4];
            }
#pragma unroll
            for (int nt = 0; nt < 4; nt++) {
                const uint32_t* base = bs + (ks * 8 + t) * G_BSTRIDE + wn * 32 + nt * 8 + g;
                bfr[nt][0] = base[0];
                bfr[nt][1] = base[4 * G_BSTRIDE];
            }
#pragma unroll
            for (int mt = 0; mt < 4; mt++)
#pragma unroll
                for (int nt = 0; nt < 4; nt++)
                    mma_tf32(acc[mt][nt], afr[mt], bfr[nt]);
        }

        if (kt < 31) {
            uint32_t* as2 = smem + (cur ^ 1) * G_BUF;
            uint32_t* bs2 = as2 + G_ABUF;
#pragma unroll
            for (int i = 0; i < 4; i++) {
                int idx = i * 256 + tid;
                int m = idx >> 3, q = idx & 7;
                as2[m * G_ASTRIDE + 4 * q + 0] = f2tf(ar[i].x);
                as2[m * G_ASTRIDE + 4 * q + 1] = f2tf(ar[i].y);
                as2[m * G_ASTRIDE + 4 * q + 2] = f2tf(ar[i].z);
                as2[m * G_ASTRIDE + 4 * q + 3] = f2tf(ar[i].w);
                int k = idx >> 5, qn = idx & 31;
                bs2[k * G_BSTRIDE + 4 * qn + 0] = f2tf(br[i].x);
                bs2[k * G_BSTRIDE + 4 * qn + 1] = f2tf(br[i].y);
                bs2[k * G_BSTRIDE + 4 * qn + 2] = f2tf(br[i].z);
                bs2[k * G_BSTRIDE + 4 * qn + 3] = f2tf(br[i].w);
            }
        }
        __syncthreads();
    }

    // epilogue: bias + store
#pragma unroll
    for (int mt = 0; mt < 4; mt++) {
        const int r0 = m0 + wm * 64 + mt * 16 + g;
        const int r1 = r0 + 8;
#pragma unroll
        for (int nt = 0; nt < 4; nt++) {
            const int c = n0 + wn * 32 + nt * 8 + 2 * t;
            const float b0 = bias[c], b1 = bias[c + 1];
            float2 o0, o1;
            o0.x = acc[mt][nt][0] + b0; o0.y = acc[mt][nt][1] + b1;
            o1.x = acc[mt][nt][2] + b0; o1.y = acc[mt][nt][3] + b1;
            *(float2*)&C[(size_t)r0 * 1024 + c] = o0;
            *(float2*)&C[(size_t)r1 * 1024 + c] = o1;
        }
    }
}

__global__ __launch_bounds__(256, 1) void qkv_gemm_tc(
    const float* __restrict__ A,
    const float* __restrict__ Wq, const float* __restrict__ bq,
    const float* __restrict__ Wk, const float* __restrict__ bk,
    const float* __restrict__ Wv, const float* __restrict__ bv)
{
    const float* W; const float* bias; float* C;
    if (blockIdx.z == 0)      { W = Wq; bias = bq; C = g_q; }
    else if (blockIdx.z == 1) { W = Wk; bias = bk; C = g_k; }
    else                      { W = Wv; bias = bv; C = g_v; }
    gemm_tc_body(A, W, bias, C);
}

__global__ __launch_bounds__(256, 1) void out_gemm_tc(
    const float* __restrict__ W, const float* __restrict__ bias,
    float* __restrict__ out)
{
    gemm_tc_body(g_ctx, W, bias, out);
}

// ---------------------------------------------------------------------------
// Flash attention with tf32 mma. q-tile=128, kv-tile=128, HD=64, 256 threads.
// S phase: warps 2x4 (tile 64x32).  PV phase: warps 4x2 (tile 32x32).
// smem (words): Qs[128*68] Ks[128*68] Vs[128*72] Ps[128*132] mask[128] m/l/al[128]
// ---------------------------------------------------------------------------
#define QS_OFF 0
#define KS_OFF 8704
#define VS_OFF 17408
#define PS_OFF 26624
#define MK_OFF 43520
#define M_OFF  43648
#define L_OFF  43776
#define AL_OFF 43904
#define ATTN_WORDS 44032
#define ATTN_SMEM (ATTN_WORDS * 4)

__global__ __launch_bounds__(256, 1) void attn_tc(const float* __restrict__ mask,
                                                  float* __restrict__ ctx)
{
    extern __shared__ float smemf[];
    uint32_t* smem = (uint32_t*)smemf;
    float* Qs = smemf + QS_OFF;     // [q][d]  stride 68
    float* Ks = smemf + KS_OFF;     // [kv][d] stride 68
    float* Vs = smemf + VS_OFF;     // [kv][d] stride 72
    float* Ps = smemf + PS_OFF;     // [q][kv] stride 132
    float* mk = smemf + MK_OFF;
    float* m_sh = smemf + M_OFF;
    float* l_sh = smemf + L_OFF;
    float* al_sh = smemf + AL_OFF;

    const int tid  = threadIdx.x;
    const int warp = tid >> 5;
    const int lane = tid & 31;
    const int g    = lane >> 2;
    const int t    = lane & 3;
    const int wm = warp >> 2, wn = warp & 3;   // S phase
    const int pm = warp >> 1, pn = warp & 1;   // PV phase

    const int b  = blockIdx.y / HH;
    const int h  = blockIdx.y % HH;
    const int q0 = blockIdx.x * 128;

    const float* qg = g_q + ((size_t)b * LL + q0) * DD + h * HDD;
    const float* kb = g_k + (size_t)b * LL * DD + h * HDD;
    const float* vb = g_v + (size_t)b * LL * DD + h * HDD;
    const float* mrow = mask + (size_t)b * LL;

    // Load Q (scaled, tf32)
#pragma unroll
    for (int i = 0; i < 8; i++) {
        int idx = i * 256 + tid;
        int r = idx >> 4, q4 = idx & 15;
        float4 v = *(const float4*)&qg[(size_t)r * DD + 4 * q4];
        uint32_t* dst = smem + QS_OFF + r * 68 + 4 * q4;
        dst[0] = f2tf(v.x * 0.125f);
        dst[1] = f2tf(v.y * 0.125f);
        dst[2] = f2tf(v.z * 0.125f);
        dst[3] = f2tf(v.w * 0.125f);
    }
    if (tid < 128) { m_sh[tid] = -INFINITY; l_sh[tid] = 0.0f; }

    float oacc[2][4][4];
#pragma unroll
    for (int mt = 0; mt < 2; mt++)
#pragma unroll
        for (int nt = 0; nt < 4; nt++)
#pragma unroll
            for (int c = 0; c < 4; c++) oacc[mt][nt][c] = 0.0f;

#pragma unroll 1
    for (int kt = 0; kt < LL / 128; kt++) {
        __syncthreads();   // previous PV done before overwriting Ks/Vs/Ps
        const float* kg = kb + (size_t)kt * 128 * DD;
        const float* vg = vb + (size_t)kt * 128 * DD;
#pragma unroll
        for (int i = 0; i < 8; i++) {
            int idx = i * 256 + tid;
            int r = idx >> 4, q4 = idx & 15;
            float4 kv4 = *(const float4*)&kg[(size_t)r * DD + 4 * q4];
            uint32_t* kd = smem + KS_OFF + r * 68 + 4 * q4;
            kd[0] = f2tf(kv4.x); kd[1] = f2tf(kv4.y);
            kd[2] = f2tf(kv4.z); kd[3] = f2tf(kv4.w);
            float4 vv4 = *(const float4*)&vg[(size_t)r * DD + 4 * q4];
            uint32_t* vd = smem + VS_OFF + r * 72 + 4 * q4;
            vd[0] = f2tf(vv4.x); vd[1] = f2tf(vv4.y);
            vd[2] = f2tf(vv4.z); vd[3] = f2tf(vv4.w);
        }
        if (tid < 128) mk[tid] = mrow[kt * 128 + tid];
        __syncthreads();

        // ---- S = Q @ K^T ----
        float sacc[4][4][4];
#pragma unroll
        for (int mt = 0; mt < 4; mt++)
#pragma unroll
            for (int nt = 0; nt < 4; nt++)
#pragma unroll
                for (int c = 0; c < 4; c++) sacc[mt][nt][c] = 0.0f;

#pragma unroll
        for (int ks = 0; ks < 8; ks++) {
            uint32_t afr[4][4], bfr[4][2];
#pragma unroll
            for (int mt = 0; mt < 4; mt++) {
                const uint32_t* base = smem + QS_OFF + (wm * 64 + mt * 16 + g) * 68 + ks * 8 + t;
                afr[mt][0] = base[0];
                afr[mt][1] = base[8 * 68];
                afr[mt][2] = base[4];
                afr[mt][3] = base[8 * 68 + 4];
            }
#pragma unroll
            for (int nt = 0; nt < 4; nt++) {
                const uint32_t* base = smem + KS_OFF + (wn * 32 + nt * 8 + g) * 68 + ks * 8 + t;
                bfr[nt][0] = base[0];
                bfr[nt][1] = base[4];
            }
#pragma unroll
            for (int mt = 0; mt < 4; mt++)
#pragma unroll
                for (int nt = 0; nt < 4; nt++)
                    mma_tf32(sacc[mt][nt], afr[mt], bfr[nt]);
        }

        // write S + mask to Ps
#pragma unroll
        for (int mt = 0; mt < 4; mt++) {
            const int r0 = wm * 64 + mt * 16 + g;
#pragma unroll
            for (int nt = 0; nt < 4; nt++) {
                const int c = wn * 32 + nt * 8 + 2 * t;
                const float mk0 = mk[c], mk1 = mk[c + 1];
                float2 s0, s1;
                s0.x = sacc[mt][nt][0] + mk0; s0.y = sacc[mt][nt][1] + mk1;
                s1.x = sacc[mt][nt][2] + mk0; s1.y = sacc[mt][nt][3] + mk1;
                *(float2*)&Ps[r0 * 132 + c]       = s0;
                *(float2*)&Ps[(r0 + 8) * 132 + c] = s1;
            }
        }
        __syncthreads();

        // ---- online softmax: 2 lanes per row ----
        {
            const int r = tid >> 1, half = tid & 1;
            float* prow = &Ps[r * 132 + half * 64];
            float mx = -INFINITY;
#pragma unroll
            for (int i = 0; i < 16; i++) {
                float4 v = *(const float4*)&prow[i * 4];
                mx = fmaxf(mx, fmaxf(fmaxf(v.x, v.y), fmaxf(v.z, v.w)));
            }
            mx = fmaxf(mx, __shfl_xor_sync(0xFFFFFFFF, mx, 1));
            const float mold = m_sh[r];
            const float mnew = fmaxf(mold, mx);
            const float a = __expf(mold - mnew);
            float ssum = 0.0f;
            uint32_t* prowu = (uint32_t*)prow;
#pragma unroll
            for (int i = 0; i < 16; i++) {
                float4 v = *(const float4*)&prow[i * 4];
                float p0 = __expf(v.x - mnew);
                float p1 = __expf(v.y - mnew);
                float p2 = __expf(v.z - mnew);
                float p3 = __expf(v.w - mnew);
                ssum += (p0 + p1) + (p2 + p3);
                prowu[i * 4 + 0] = f2tf(p0);
                prowu[i * 4 + 1] = f2tf(p1);
                prowu[i * 4 + 2] = f2tf(p2);
                prowu[i * 4 + 3] = f2tf(p3);
            }
            ssum += __shfl_xor_sync(0xFFFFFFFF, ssum, 1);
            l_sh[r] = l_sh[r] * a + ssum;
            m_sh[r] = mnew;
            al_sh[r] = a;
        }
        __syncthreads();

        // ---- O = O*alpha + P @ V ----
#pragma unroll
        for (int mt = 0; mt < 2; mt++) {
            const int r0 = pm * 32 + mt * 16 + g;
            const float a0 = al_sh[r0], a1 = al_sh[r0 + 8];
#pragma unroll
            for (int nt = 0; nt < 4; nt++) {
                oacc[mt][nt][0] *= a0; oacc[mt][nt][1] *= a0;
                oacc[mt][nt][2] *= a1; oacc[mt][nt][3] *= a1;
            }
        }
#pragma unroll
        for (int ks = 0; ks < 16; ks++) {
            uint32_t afr[2][4], bfr[4][2];
#pragma unroll
            for (int mt = 0; mt < 2; mt++) {
                const uint32_t* base = smem + PS_OFF + (pm * 32 + mt * 16 + g) * 132 + ks * 8 + t;
                afr[mt][0] = base[0];
                afr[mt][1] = base[8 * 132];
                afr[mt][2] = base[4];
                afr[mt][3] = base[8 * 132 + 4];
            }
#pragma unroll
            for (int nt = 0; nt < 4; nt++) {
                const uint32_t* base = smem + VS_OFF + (ks * 8 + t) * 72 + pn * 32 + nt * 8 + g;
                bfr[nt][0] = base[0];
                bfr[nt][1] = base[4 * 72];
            }
#pragma unroll
            for (int mt = 0; mt < 2; mt++)
#pragma unroll
                for (int nt = 0; nt < 4; nt++)
                    mma_tf32(oacc[mt][nt], afr[mt], bfr[nt]);
        }
    }
    __syncthreads();

    // normalize + write ctx [B,L,D]
#pragma unroll
    for (int mt = 0; mt < 2; mt++) {
        const int r0 = pm * 32 + mt * 16 + g;
        const int r1 = r0 + 8;
        const float inv0 = 1.0f / l_sh[r0];
        const float inv1 = 1.0f / l_sh[r1];
#pragma unroll
        for (int nt = 0; nt < 4; nt++) {
            const int c = pn * 32 + nt * 8 + 2 * t;
            float2 o0, o1;
            o0.x = oacc[mt][nt][0] * inv0; o0.y = oacc[mt][nt][1] * inv0;
            o1.x = oacc[mt][nt][2] * inv1; o1.y = oacc[mt][nt][3] * inv1;
            *(float2*)&ctx[((size_t)b * LL + q0 + r0) * DD + h * HDD + c] = o0;
            *(float2*)&ctx[((size_t)b * LL + q0 + r1) * DD + h * HDD + c] = o1;
        }
    }
}

// ---------------------------------------------------------------------------
extern "C" void kernel_launch(void* const* d_in, const int* in_sizes, int n_in,
                              void* d_out, int out_size)
{
    const float* hs   = (const float*)d_in[0];
    const float* mask = (const float*)d_in[1];
    const float* Wq = (const float*)d_in[2]; const float* bq = (const float*)d_in[3];
    const float* Wk = (const float*)d_in[4]; const float* bk = (const float*)d_in[5];
    const float* Wv = (const float*)d_in[6]; const float* bv = (const float*)d_in[7];
    const float* Wo = (const float*)d_in[8]; const float* bo = (const float*)d_in[9];
    float* out = (float*)d_out;

    cudaFuncSetAttribute(qkv_gemm_tc, cudaFuncAttributeMaxDynamicSharedMemorySize, GEMM_SMEM);
    cudaFuncSetAttribute(out_gemm_tc, cudaFuncAttributeMaxDynamicSharedMemorySize, GEMM_SMEM);
    cudaFuncSetAttribute(attn_tc, cudaFuncAttributeMaxDynamicSharedMemorySize, ATTN_SMEM);

    float* ctx_ptr = nullptr;
    cudaGetSymbolAddress((void**)&ctx_ptr, g_ctx);

    // 1) QKV projections
    dim3 ggrid(1024 / 128, 4096 / 128, 3);
    qkv_gemm_tc<<<ggrid, 256, GEMM_SMEM>>>(hs, Wq, bq, Wk, bk, Wv, bv);

    // 2) Attention
    dim3 agrid(LL / 128, BB * HH);
    attn_tc<<<agrid, 256, ATTN_SMEM>>>(mask, ctx_ptr);

    // 3) Output projection
    dim3 ogrid(1024 / 128, 4096 / 128, 1);
    out_gemm_tc<<<ogrid, 256, GEMM_SMEM>>>(Wo, bo, out);
}